// round 1
// baseline (speedup 1.0000x reference)
#include <cuda_runtime.h>
#include <math.h>

#define BB    4
#define CC    256
#define SL    2304     // 48*48
#define SG    144      // 12*12
#define HEADS 8
#define HD    32

// ---------------- scratch (static device globals; no allocation) ----------------
__device__ float g_qkv   [BB*768*SL];   // local qkv  [B,768,S]
__device__ float g_qkvt  [BB*768*SL];   // local q/k/v transposed+normed [B,3,8,S,32]
__device__ float g_attn  [BB*CC*SL];    // local attn out [B,256,S]
__device__ float g_concat[(long)BB*512*SL]; // [B,512,S]: ch 0..255 = proj_l out, 256..511 = upsampled g
__device__ float g_h     [BB*CC*SL];    // post-f1 hidden
__device__ float g_xc    [BB*CC*SG];    // pooled x
__device__ float g_qkvg  [BB*768*SG];
__device__ float g_qkvtg [BB*768*SG];
__device__ float g_attng [BB*CC*SG];
__device__ float g_g     [BB*CC*SG];    // global branch output (12x12)

// ---------------- generic conv1x1 GEMM: Y[b,o,s] = sum_c W[o,c]*X[b,c,s] (+bias)(+gelu) ----
// BM=64 (o), BN=64 (s), BK=16, 16x16 threads, 4x4 per thread.
__global__ void gemm_kernel(const float* __restrict__ X, const float* __restrict__ Wm,
                            const float* __restrict__ bias, float* __restrict__ Y,
                            int O, int Cin, int Ssz, long xBS, long yBS, int doGelu)
{
    __shared__ float Ws[16][64];
    __shared__ float Xs[16][64];
    const int tx = threadIdx.x, ty = threadIdx.y;
    const int tid = ty * 16 + tx;
    const int s0 = blockIdx.x * 64;
    const int o0 = blockIdx.y * 64;
    const int b  = blockIdx.z;
    const float* Xb = X + (long)b * xBS;
    const bool full = (s0 + 64 <= Ssz);

    const int lw_o = tid >> 2;        // 0..63
    const int lw_c = (tid & 3) * 4;   // 0,4,8,12
    const int lx_c = tid >> 4;        // 0..15
    const int lx_s = (tid & 15) * 4;  // 0..60

    float acc[4][4] = {};

    for (int c0 = 0; c0 < Cin; c0 += 16) {
        float4 wv = *(const float4*)(Wm + (long)(o0 + lw_o) * Cin + c0 + lw_c);
        Ws[lw_c + 0][lw_o] = wv.x; Ws[lw_c + 1][lw_o] = wv.y;
        Ws[lw_c + 2][lw_o] = wv.z; Ws[lw_c + 3][lw_o] = wv.w;

        const float* xrow = Xb + (long)(c0 + lx_c) * Ssz + s0 + lx_s;
        if (full) {
            float4 xv = *(const float4*)xrow;
            Xs[lx_c][lx_s + 0] = xv.x; Xs[lx_c][lx_s + 1] = xv.y;
            Xs[lx_c][lx_s + 2] = xv.z; Xs[lx_c][lx_s + 3] = xv.w;
        } else {
            #pragma unroll
            for (int i = 0; i < 4; i++)
                Xs[lx_c][lx_s + i] = (s0 + lx_s + i < Ssz) ? xrow[i] : 0.f;
        }
        __syncthreads();

        #pragma unroll
        for (int c = 0; c < 16; c++) {
            float4 a = *(const float4*)&Ws[c][ty * 4];
            float4 x = *(const float4*)&Xs[c][tx * 4];
            acc[0][0] += a.x * x.x; acc[0][1] += a.x * x.y; acc[0][2] += a.x * x.z; acc[0][3] += a.x * x.w;
            acc[1][0] += a.y * x.x; acc[1][1] += a.y * x.y; acc[1][2] += a.y * x.z; acc[1][3] += a.y * x.w;
            acc[2][0] += a.z * x.x; acc[2][1] += a.z * x.y; acc[2][2] += a.z * x.z; acc[2][3] += a.z * x.w;
            acc[3][0] += a.w * x.x; acc[3][1] += a.w * x.y; acc[3][2] += a.w * x.z; acc[3][3] += a.w * x.w;
        }
        __syncthreads();
    }

    #pragma unroll
    for (int i = 0; i < 4; i++) {
        int o = o0 + ty * 4 + i;
        float bv = bias ? bias[o] : 0.f;
        #pragma unroll
        for (int j = 0; j < 4; j++) {
            int s = s0 + tx * 4 + j;
            if (s < Ssz) {
                float v = acc[i][j] + bv;
                if (doGelu) v = 0.5f * v * (1.f + erff(v * 0.70710678118654752f));
                Y[(long)b * yBS + (long)o * Ssz + s] = v;
            }
        }
    }
}

// ---------- transpose [B,768,S] -> [B,3,8,S,32] with L2-norm on q (part 0) and k (part 1) ----
__global__ void tnorm_kernel(const float* __restrict__ qkv, float* __restrict__ qkvt, int Ssz)
{
    __shared__ float sm[32][33];
    const int bp = blockIdx.y;
    const int b = bp / 24;
    const int rem = bp % 24;
    const int part = rem / 8;
    const int h = rem % 8;
    const int s0 = blockIdx.x * 32;
    const int tx = threadIdx.x, ty = threadIdx.y;

    {
        int s = s0 + tx;
        float v = 0.f;
        if (s < Ssz) v = qkv[((long)b * 768 + part * 256 + h * 32 + ty) * Ssz + s];
        sm[ty][tx] = v;
    }
    __syncthreads();

    float v = sm[tx][ty];   // warp: ty fixed (s row), tx = lane = d
    if (part < 2) {
        float sq = v * v;
        #pragma unroll
        for (int off = 16; off; off >>= 1) sq += __shfl_xor_sync(0xffffffffu, sq, off);
        float n = sqrtf(sq);
        v = v / fmaxf(n, 1e-12f);
    }
    int s = s0 + ty;
    if (s < Ssz)
        qkvt[(((long)(b * 3 + part) * 8 + h) * Ssz + s) * 32 + tx] = v;
}

// ---------------- flash attention (no running max needed: |logit| <= 0.177) ----------------
// grid: (B*heads, ceil(S/128)), block 128; each thread owns one q row.
__global__ void attn_kernel(const float* __restrict__ qkvt, float* __restrict__ out, int Ssz)
{
    __shared__ float ks[64][32];
    __shared__ float vs[64][32];
    const int bh = blockIdx.x;
    const int b = bh >> 3, h = bh & 7;
    const long base = ((long)(b * 3) * HEADS + h) * Ssz * HD;
    const float* Q = qkvt + base;
    const float* K = Q + (long)HEADS * Ssz * HD;
    const float* V = Q + 2L * HEADS * Ssz * HD;
    const int tid = threadIdx.x;
    const int row = blockIdx.y * 128 + tid;
    const bool valid = row < Ssz;

    float q[32];
    if (valid) {
        const float4* qp = (const float4*)(Q + (long)row * 32);
        #pragma unroll
        for (int i = 0; i < 8; i++) {
            float4 t = qp[i];
            q[4*i] = t.x; q[4*i+1] = t.y; q[4*i+2] = t.z; q[4*i+3] = t.w;
        }
    }
    float acc[32] = {0.f};
    float l = 0.f;

    for (int j0 = 0; j0 < Ssz; j0 += 64) {
        int cnt = min(64, Ssz - j0);
        int nf4 = cnt * 8;
        const float4* kp = (const float4*)(K + (long)j0 * 32);
        const float4* vp = (const float4*)(V + (long)j0 * 32);
        #pragma unroll
        for (int t = 0; t < 4; t++) {
            int i = tid + t * 128;
            if (i < nf4) { ((float4*)ks)[i] = kp[i]; ((float4*)vs)[i] = vp[i]; }
        }
        __syncthreads();
        if (valid) {
            for (int j = 0; j < cnt; j++) {
                const float4* kr = (const float4*)ks[j];
                float dot = 0.f;
                #pragma unroll
                for (int i = 0; i < 8; i++) {
                    float4 kv = kr[i];
                    dot += q[4*i] * kv.x + q[4*i+1] * kv.y + q[4*i+2] * kv.z + q[4*i+3] * kv.w;
                }
                float p = __expf(dot * 0.17677669529663687f);
                l += p;
                const float4* vr = (const float4*)vs[j];
                #pragma unroll
                for (int i = 0; i < 8; i++) {
                    float4 vv = vr[i];
                    acc[4*i]   += p * vv.x; acc[4*i+1] += p * vv.y;
                    acc[4*i+2] += p * vv.z; acc[4*i+3] += p * vv.w;
                }
            }
        }
        __syncthreads();
    }

    if (valid) {
        float inv = 1.f / l;
        #pragma unroll
        for (int d = 0; d < 32; d++)
            out[((long)(b * CC) + h * HD + d) * Ssz + row] = acc[d] * inv;
    }
}

// ---------------- 4x4 average pool: [B,256,48,48] -> [B,256,12,12] ----------------
__global__ void avgpool_kernel(const float* __restrict__ x, float* __restrict__ xc)
{
    int idx = blockIdx.x * blockDim.x + threadIdx.x;
    if (idx >= BB * CC * SG) return;
    int p = idx % SG;
    int c = (idx / SG) % CC;
    int b = idx / (SG * CC);
    int i = p / 12, j = p % 12;
    const float* xp = x + ((long)b * CC + c) * SL;
    float s = 0.f;
    #pragma unroll
    for (int dy = 0; dy < 4; dy++)
        #pragma unroll
        for (int dx = 0; dx < 4; dx++)
            s += xp[(i * 4 + dy) * 48 + j * 4 + dx];
    xc[idx] = s * (1.f / 16.f);
}

// ---------------- bilinear 12x12 -> 48x48 (half-pixel centers), into concat ch 256..511 ----
__global__ void upsample_kernel(const float* __restrict__ g, float* __restrict__ concat)
{
    int idx = blockIdx.x * blockDim.x + threadIdx.x;
    if (idx >= BB * CC * SL) return;
    int p = idx % SL;
    int c = (idx / SL) % CC;
    int b = idx / (SL * CC);
    int y = p / 48, x = p % 48;
    float fy = (y + 0.5f) * 0.25f - 0.5f;
    float fx = (x + 0.5f) * 0.25f - 0.5f;
    int y0 = (int)floorf(fy), x0 = (int)floorf(fx);
    float wy = fy - y0, wx = fx - x0;
    int ya = min(11, max(0, y0)), yb = min(11, max(0, y0 + 1));
    int xa = min(11, max(0, x0)), xb = min(11, max(0, x0 + 1));
    const float* gp = g + ((long)b * CC + c) * SG;
    float v00 = gp[ya * 12 + xa], v01 = gp[ya * 12 + xb];
    float v10 = gp[yb * 12 + xa], v11 = gp[yb * 12 + xb];
    float v = (1.f - wy) * ((1.f - wx) * v00 + wx * v01)
            +        wy  * ((1.f - wx) * v10 + wx * v11);
    concat[((long)b * 512 + 256 + c) * SL + p] = v;
}

// ---------------- launch ----------------
extern "C" void kernel_launch(void* const* d_in, const int* in_sizes, int n_in,
                              void* d_out, int out_size)
{
    const float* x        = (const float*)d_in[0];
    const float* w_qkv_l  = (const float*)d_in[1];
    const float* w_proj_l = (const float*)d_in[2];
    const float* b_proj_l = (const float*)d_in[3];
    const float* w_qkv_g  = (const float*)d_in[4];
    const float* w_proj_g = (const float*)d_in[5];
    const float* b_proj_g = (const float*)d_in[6];
    const float* w_f1     = (const float*)d_in[7];
    const float* b_f1     = (const float*)d_in[8];
    const float* w_f2     = (const float*)d_in[9];
    const float* b_f2     = (const float*)d_in[10];
    float* out = (float*)d_out;

    float *qkv, *qkvt, *attn, *concat, *hbuf, *xc, *qkvg, *qkvtg, *attng, *gg;
    cudaGetSymbolAddress((void**)&qkv,    g_qkv);
    cudaGetSymbolAddress((void**)&qkvt,   g_qkvt);
    cudaGetSymbolAddress((void**)&attn,   g_attn);
    cudaGetSymbolAddress((void**)&concat, g_concat);
    cudaGetSymbolAddress((void**)&hbuf,   g_h);
    cudaGetSymbolAddress((void**)&xc,     g_xc);
    cudaGetSymbolAddress((void**)&qkvg,   g_qkvg);
    cudaGetSymbolAddress((void**)&qkvtg,  g_qkvtg);
    cudaGetSymbolAddress((void**)&attng,  g_attng);
    cudaGetSymbolAddress((void**)&gg,     g_g);

    dim3 blk(16, 16);

    // local branch
    gemm_kernel<<<dim3(SL / 64, 768 / 64, BB), blk>>>(x, w_qkv_l, nullptr, qkv,
                                                      768, 256, SL, 256L * SL, 768L * SL, 0);
    tnorm_kernel<<<dim3(SL / 32, BB * 24), dim3(32, 32)>>>(qkv, qkvt, SL);
    attn_kernel<<<dim3(BB * HEADS, (SL + 127) / 128), 128>>>(qkvt, attn, SL);
    gemm_kernel<<<dim3(SL / 64, 256 / 64, BB), blk>>>(attn, w_proj_l, b_proj_l, concat,
                                                      256, 256, SL, 256L * SL, 512L * SL, 0);

    // global branch
    avgpool_kernel<<<(BB * CC * SG + 255) / 256, 256>>>(x, xc);
    gemm_kernel<<<dim3((SG + 63) / 64, 768 / 64, BB), blk>>>(xc, w_qkv_g, nullptr, qkvg,
                                                             768, 256, SG, 256L * SG, 768L * SG, 0);
    tnorm_kernel<<<dim3((SG + 31) / 32, BB * 24), dim3(32, 32)>>>(qkvg, qkvtg, SG);
    attn_kernel<<<dim3(BB * HEADS, (SG + 127) / 128), 128>>>(qkvtg, attng, SG);
    gemm_kernel<<<dim3((SG + 63) / 64, 256 / 64, BB), blk>>>(attng, w_proj_g, b_proj_g, gg,
                                                             256, 256, SG, 256L * SG, 256L * SG, 0);
    upsample_kernel<<<(BB * CC * SL + 255) / 256, 256>>>(gg, concat);

    // fusion head
    gemm_kernel<<<dim3(SL / 64, 256 / 64, BB), blk>>>(concat, w_f1, b_f1, hbuf,
                                                      256, 512, SL, 512L * SL, 256L * SL, 1);
    gemm_kernel<<<dim3(SL / 64, 256 / 64, BB), blk>>>(hbuf, w_f2, b_f2, out,
                                                      256, 256, SL, 256L * SL, 256L * SL, 0);
}

// round 4
// speedup vs baseline: 1.0957x; 1.0957x over previous
#include <cuda_runtime.h>
#include <math.h>

#define BB    4
#define CC    256
#define SL    2304     // 48*48
#define SG    144      // 12*12
#define HEADS 8
#define HD    32

typedef unsigned long long u64;

// ---------------- f32x2 packed helpers (Blackwell sm_100+) ----------------
__device__ __forceinline__ u64 ffma2(u64 a, u64 b, u64 c) {
    u64 d;
    asm("fma.rn.f32x2 %0, %1, %2, %3;" : "=l"(d) : "l"(a), "l"(b), "l"(c));
    return d;
}
__device__ __forceinline__ u64 pack2(float x, float y) {
    u64 d;
    asm("mov.b64 %0, {%1, %2};" : "=l"(d) : "f"(x), "f"(y));
    return d;
}
__device__ __forceinline__ float2 unpack2(u64 v) {
    float2 r;
    asm("mov.b64 {%0, %1}, %2;" : "=f"(r.x), "=f"(r.y) : "l"(v));
    return r;
}
// 128-bit shared load as two packed-f32x2 operands. Plain C++ load so the
// compiler tracks the memory dependence (the R3 asm version was CSE'd across
// __syncthreads, reading stale tiles).
__device__ __forceinline__ void lds2(const float* p, u64& a, u64& b) {
    double2 t = *(const double2*)p;
    a = (u64)__double_as_longlong(t.x);
    b = (u64)__double_as_longlong(t.y);
}

// ---------------- scratch (static device globals; no allocation) ----------------
__device__ float g_qkv   [BB*768*SL];
__device__ float g_qkvt  [BB*768*SL];
__device__ float g_attn  [BB*CC*SL];
__device__ float g_concat[(long)BB*512*SL];
__device__ float g_h     [BB*CC*SL];
__device__ float g_xc    [BB*CC*SG];
__device__ float g_qkvg  [BB*768*SG];
__device__ float g_qkvtg [BB*768*SG];
__device__ float g_attng [BB*CC*SG];
__device__ float g_g     [BB*CC*SG];

// ---------------- conv1x1 GEMM: Y[b,o,s] = sum_c W[o,c]*X[b,c,s] (+bias)(+gelu) ----
// Tile: 128(o) x 64(s) x 16(c). 256 threads (16x16), 8x4 microtile via f32x2.
__global__ void gemm_kernel(const float* __restrict__ X, const float* __restrict__ Wm,
                            const float* __restrict__ bias, float* __restrict__ Y,
                            int Cin, int Ssz, long xBS, long yBS, int doGelu)
{
    __shared__ __align__(16) float Ws[16][128];
    __shared__ __align__(16) float Xs[16][64];
    const int tx = threadIdx.x, ty = threadIdx.y;   // 16x16
    const int tid = ty * 16 + tx;
    const int s0 = blockIdx.x * 64;
    const int o0 = blockIdx.y * 128;
    const int b  = blockIdx.z;
    const float* Xb = X + (long)b * xBS;
    const bool full = (s0 + 64 <= Ssz);

    const int lw_o = tid >> 1;          // 0..127
    const int lw_c = (tid & 1) * 8;     // 0 or 8
    const int lx_c = tid >> 4;          // 0..15
    const int lx_s = (tid & 15) * 4;

    u64 acc[8][2];
    #pragma unroll
    for (int i = 0; i < 8; i++) { acc[i][0] = 0ULL; acc[i][1] = 0ULL; }

    for (int c0 = 0; c0 < Cin; c0 += 16) {
        {
            const float* wrow = Wm + (long)(o0 + lw_o) * Cin + c0 + lw_c;
            float4 w0 = *(const float4*)wrow;
            float4 w1 = *(const float4*)(wrow + 4);
            Ws[lw_c + 0][lw_o] = w0.x; Ws[lw_c + 1][lw_o] = w0.y;
            Ws[lw_c + 2][lw_o] = w0.z; Ws[lw_c + 3][lw_o] = w0.w;
            Ws[lw_c + 4][lw_o] = w1.x; Ws[lw_c + 5][lw_o] = w1.y;
            Ws[lw_c + 6][lw_o] = w1.z; Ws[lw_c + 7][lw_o] = w1.w;
        }
        {
            const float* xrow = Xb + (long)(c0 + lx_c) * Ssz + s0 + lx_s;
            if (full) {
                float4 xv = *(const float4*)xrow;
                Xs[lx_c][lx_s + 0] = xv.x; Xs[lx_c][lx_s + 1] = xv.y;
                Xs[lx_c][lx_s + 2] = xv.z; Xs[lx_c][lx_s + 3] = xv.w;
            } else {
                #pragma unroll
                for (int i = 0; i < 4; i++)
                    Xs[lx_c][lx_s + i] = (s0 + lx_s + i < Ssz) ? xrow[i] : 0.f;
            }
        }
        __syncthreads();

        #pragma unroll
        for (int c = 0; c < 16; c++) {
            u64 x01, x23;
            lds2(&Xs[c][tx * 4], x01, x23);
            float4 a0 = *(const float4*)&Ws[c][ty * 8];
            float4 a1 = *(const float4*)&Ws[c][ty * 8 + 4];
            u64 p;
            p = pack2(a0.x, a0.x); acc[0][0] = ffma2(p, x01, acc[0][0]); acc[0][1] = ffma2(p, x23, acc[0][1]);
            p = pack2(a0.y, a0.y); acc[1][0] = ffma2(p, x01, acc[1][0]); acc[1][1] = ffma2(p, x23, acc[1][1]);
            p = pack2(a0.z, a0.z); acc[2][0] = ffma2(p, x01, acc[2][0]); acc[2][1] = ffma2(p, x23, acc[2][1]);
            p = pack2(a0.w, a0.w); acc[3][0] = ffma2(p, x01, acc[3][0]); acc[3][1] = ffma2(p, x23, acc[3][1]);
            p = pack2(a1.x, a1.x); acc[4][0] = ffma2(p, x01, acc[4][0]); acc[4][1] = ffma2(p, x23, acc[4][1]);
            p = pack2(a1.y, a1.y); acc[5][0] = ffma2(p, x01, acc[5][0]); acc[5][1] = ffma2(p, x23, acc[5][1]);
            p = pack2(a1.z, a1.z); acc[6][0] = ffma2(p, x01, acc[6][0]); acc[6][1] = ffma2(p, x23, acc[6][1]);
            p = pack2(a1.w, a1.w); acc[7][0] = ffma2(p, x01, acc[7][0]); acc[7][1] = ffma2(p, x23, acc[7][1]);
        }
        __syncthreads();
    }

    #pragma unroll
    for (int i = 0; i < 8; i++) {
        int o = o0 + ty * 8 + i;
        float bv = bias ? bias[o] : 0.f;
        float2 p0 = unpack2(acc[i][0]);
        float2 p1 = unpack2(acc[i][1]);
        float vals[4] = {p0.x, p0.y, p1.x, p1.y};
        #pragma unroll
        for (int j = 0; j < 4; j++) {
            int s = s0 + tx * 4 + j;
            if (s < Ssz) {
                float v = vals[j] + bv;
                if (doGelu) v = 0.5f * v * (1.f + erff(v * 0.70710678118654752f));
                Y[(long)b * yBS + (long)o * Ssz + s] = v;
            }
        }
    }
}

// ---------- transpose [B,768,S] -> [B,3,8,S,32] with L2-norm on q/k ----------
__global__ void tnorm_kernel(const float* __restrict__ qkv, float* __restrict__ qkvt, int Ssz)
{
    __shared__ float sm[32][33];
    const int bp = blockIdx.y;
    const int b = bp / 24;
    const int rem = bp % 24;
    const int part = rem / 8;
    const int h = rem % 8;
    const int s0 = blockIdx.x * 32;
    const int tx = threadIdx.x, ty = threadIdx.y;

    {
        int s = s0 + tx;
        float v = 0.f;
        if (s < Ssz) v = qkv[((long)b * 768 + part * 256 + h * 32 + ty) * Ssz + s];
        sm[ty][tx] = v;
    }
    __syncthreads();

    float v = sm[tx][ty];
    if (part < 2) {
        float sq = v * v;
        #pragma unroll
        for (int off = 16; off; off >>= 1) sq += __shfl_xor_sync(0xffffffffu, sq, off);
        float n = sqrtf(sq);
        v = v / fmaxf(n, 1e-12f);
    }
    int s = s0 + ty;
    if (s < Ssz)
        qkvt[(((long)(b * 3 + part) * 8 + h) * Ssz + s) * 32 + tx] = v;
}

// ---------------- flash attention with f32x2 packed math ----------------
// |logit| <= 0.177 (unit q,k) so no running max. grid (B*H, ceil(S/128)), block 128.
__global__ void attn_kernel(const float* __restrict__ qkvt, float* __restrict__ out, int Ssz)
{
    __shared__ __align__(16) float ks[64][32];
    __shared__ __align__(16) float vs[64][32];
    const int bh = blockIdx.x;
    const int b = bh >> 3, h = bh & 7;
    const long base = ((long)(b * 3) * HEADS + h) * Ssz * HD;
    const float* Q = qkvt + base;
    const float* K = Q + (long)HEADS * Ssz * HD;
    const float* V = Q + 2L * HEADS * Ssz * HD;
    const int tid = threadIdx.x;
    const int row = blockIdx.y * 128 + tid;
    const bool valid = row < Ssz;

    u64 q2[16];
    if (valid) {
        const double2* qp = (const double2*)(Q + (long)row * 32);
        #pragma unroll
        for (int i = 0; i < 8; i++) {
            double2 t = qp[i];
            q2[2 * i]     = (u64)__double_as_longlong(t.x);
            q2[2 * i + 1] = (u64)__double_as_longlong(t.y);
        }
    }
    u64 acc[16];
    #pragma unroll
    for (int i = 0; i < 16; i++) acc[i] = 0ULL;
    float l = 0.f;

    for (int j0 = 0; j0 < Ssz; j0 += 64) {
        int cnt = min(64, Ssz - j0);
        int nf4 = cnt * 8;
        const float4* kp = (const float4*)(K + (long)j0 * 32);
        const float4* vp = (const float4*)(V + (long)j0 * 32);
        #pragma unroll
        for (int t = 0; t < 4; t++) {
            int i = tid + t * 128;
            if (i < nf4) { ((float4*)ks)[i] = kp[i]; ((float4*)vs)[i] = vp[i]; }
        }
        __syncthreads();
        if (valid) {
            for (int j = 0; j < cnt; j++) {
                u64 d0 = 0ULL, d1 = 0ULL;
                #pragma unroll
                for (int i = 0; i < 8; i++) {
                    u64 k0, k1;
                    lds2(&ks[j][i * 4], k0, k1);
                    d0 = ffma2(q2[2 * i], k0, d0);
                    d1 = ffma2(q2[2 * i + 1], k1, d1);
                }
                float2 e0 = unpack2(d0), e1 = unpack2(d1);
                float dot = (e0.x + e0.y) + (e1.x + e1.y);
                float p = __expf(dot * 0.17677669529663687f);
                l += p;
                u64 pp = pack2(p, p);
                #pragma unroll
                for (int i = 0; i < 8; i++) {
                    u64 v0, v1;
                    lds2(&vs[j][i * 4], v0, v1);
                    acc[2 * i]     = ffma2(pp, v0, acc[2 * i]);
                    acc[2 * i + 1] = ffma2(pp, v1, acc[2 * i + 1]);
                }
            }
        }
        __syncthreads();
    }

    if (valid) {
        float inv = 1.f / l;
        long ob = (long)b * CC + h * HD;
        #pragma unroll
        for (int i = 0; i < 16; i++) {
            float2 t = unpack2(acc[i]);
            out[(ob + 2 * i)     * (long)Ssz + row] = t.x * inv;
            out[(ob + 2 * i + 1) * (long)Ssz + row] = t.y * inv;
        }
    }
}

// ---------------- 4x4 average pool ----------------
__global__ void avgpool_kernel(const float* __restrict__ x, float* __restrict__ xc)
{
    int idx = blockIdx.x * blockDim.x + threadIdx.x;
    if (idx >= BB * CC * SG) return;
    int p = idx % SG;
    int c = (idx / SG) % CC;
    int b = idx / (SG * CC);
    int i = p / 12, j = p % 12;
    const float* xp = x + ((long)b * CC + c) * SL;
    float s = 0.f;
    #pragma unroll
    for (int dy = 0; dy < 4; dy++)
        #pragma unroll
        for (int dx = 0; dx < 4; dx++)
            s += xp[(i * 4 + dy) * 48 + j * 4 + dx];
    xc[idx] = s * (1.f / 16.f);
}

// ---------------- bilinear 12x12 -> 48x48 into concat ch 256..511 ----------------
__global__ void upsample_kernel(const float* __restrict__ g, float* __restrict__ concat)
{
    int idx = blockIdx.x * blockDim.x + threadIdx.x;
    if (idx >= BB * CC * SL) return;
    int p = idx % SL;
    int c = (idx / SL) % CC;
    int b = idx / (SL * CC);
    int y = p / 48, x = p % 48;
    float fy = (y + 0.5f) * 0.25f - 0.5f;
    float fx = (x + 0.5f) * 0.25f - 0.5f;
    int y0 = (int)floorf(fy), x0 = (int)floorf(fx);
    float wy = fy - y0, wx = fx - x0;
    int ya = min(11, max(0, y0)), yb = min(11, max(0, y0 + 1));
    int xa = min(11, max(0, x0)), xb = min(11, max(0, x0 + 1));
    const float* gp = g + ((long)b * CC + c) * SG;
    float v00 = gp[ya * 12 + xa], v01 = gp[ya * 12 + xb];
    float v10 = gp[yb * 12 + xa], v11 = gp[yb * 12 + xb];
    float v = (1.f - wy) * ((1.f - wx) * v00 + wx * v01)
            +        wy  * ((1.f - wx) * v10 + wx * v11);
    concat[((long)b * 512 + 256 + c) * SL + p] = v;
}

// ---------------- launch ----------------
extern "C" void kernel_launch(void* const* d_in, const int* in_sizes, int n_in,
                              void* d_out, int out_size)
{
    const float* x        = (const float*)d_in[0];
    const float* w_qkv_l  = (const float*)d_in[1];
    const float* w_proj_l = (const float*)d_in[2];
    const float* b_proj_l = (const float*)d_in[3];
    const float* w_qkv_g  = (const float*)d_in[4];
    const float* w_proj_g = (const float*)d_in[5];
    const float* b_proj_g = (const float*)d_in[6];
    const float* w_f1     = (const float*)d_in[7];
    const float* b_f1     = (const float*)d_in[8];
    const float* w_f2     = (const float*)d_in[9];
    const float* b_f2     = (const float*)d_in[10];
    float* out = (float*)d_out;

    float *qkv, *qkvt, *attn, *concat, *hbuf, *xc, *qkvg, *qkvtg, *attng, *gg;
    cudaGetSymbolAddress((void**)&qkv,    g_qkv);
    cudaGetSymbolAddress((void**)&qkvt,   g_qkvt);
    cudaGetSymbolAddress((void**)&attn,   g_attn);
    cudaGetSymbolAddress((void**)&concat, g_concat);
    cudaGetSymbolAddress((void**)&hbuf,   g_h);
    cudaGetSymbolAddress((void**)&xc,     g_xc);
    cudaGetSymbolAddress((void**)&qkvg,   g_qkvg);
    cudaGetSymbolAddress((void**)&qkvtg,  g_qkvtg);
    cudaGetSymbolAddress((void**)&attng,  g_attng);
    cudaGetSymbolAddress((void**)&gg,     g_g);

    dim3 blk(16, 16);

    // local branch
    gemm_kernel<<<dim3(SL / 64, 768 / 128, BB), blk>>>(x, w_qkv_l, nullptr, qkv,
                                                       256, SL, 256L * SL, 768L * SL, 0);
    tnorm_kernel<<<dim3(SL / 32, BB * 24), dim3(32, 32)>>>(qkv, qkvt, SL);
    attn_kernel<<<dim3(BB * HEADS, (SL + 127) / 128), 128>>>(qkvt, attn, SL);
    gemm_kernel<<<dim3(SL / 64, 256 / 128, BB), blk>>>(attn, w_proj_l, b_proj_l, concat,
                                                       256, SL, 256L * SL, 512L * SL, 0);

    // global branch
    avgpool_kernel<<<(BB * CC * SG + 255) / 256, 256>>>(x, xc);
    gemm_kernel<<<dim3((SG + 63) / 64, 768 / 128, BB), blk>>>(xc, w_qkv_g, nullptr, qkvg,
                                                              256, SG, 256L * SG, 768L * SG, 0);
    tnorm_kernel<<<dim3((SG + 31) / 32, BB * 24), dim3(32, 32)>>>(qkvg, qkvtg, SG);
    attn_kernel<<<dim3(BB * HEADS, (SG + 127) / 128), 128>>>(qkvtg, attng, SG);
    gemm_kernel<<<dim3((SG + 63) / 64, 256 / 128, BB), blk>>>(attng, w_proj_g, b_proj_g, gg,
                                                              256, SG, 256L * SG, 256L * SG, 0);
    upsample_kernel<<<(BB * CC * SL + 255) / 256, 256>>>(gg, concat);

    // fusion head
    gemm_kernel<<<dim3(SL / 64, 256 / 128, BB), blk>>>(concat, w_f1, b_f1, hbuf,
                                                       512, SL, 512L * SL, 256L * SL, 1);
    gemm_kernel<<<dim3(SL / 64, 256 / 128, BB), blk>>>(hbuf, w_f2, b_f2, out,
                                                       256, SL, 256L * SL, 256L * SL, 0);
}

// round 5
// speedup vs baseline: 1.2901x; 1.1775x over previous
#include <cuda_runtime.h>
#include <math.h>

#define BB    4
#define CC    256
#define SL    2304     // 48*48
#define SG    144      // 12*12
#define HEADS 8
#define HD    32

typedef unsigned long long u64;

// ---------------- f32x2 packed helpers (Blackwell sm_100+) ----------------
__device__ __forceinline__ u64 ffma2(u64 a, u64 b, u64 c) {
    u64 d;
    asm("fma.rn.f32x2 %0, %1, %2, %3;" : "=l"(d) : "l"(a), "l"(b), "l"(c));
    return d;
}
__device__ __forceinline__ u64 pack2(float x, float y) {
    u64 d;
    asm("mov.b64 %0, {%1, %2};" : "=l"(d) : "f"(x), "f"(y));
    return d;
}
__device__ __forceinline__ float2 unpack2(u64 v) {
    float2 r;
    asm("mov.b64 {%0, %1}, %2;" : "=f"(r.x), "=f"(r.y) : "l"(v));
    return r;
}
// 128-bit shared/global load as two packed-f32x2 operands (compiler-visible).
__device__ __forceinline__ void lds2(const float* p, u64& a, u64& b) {
    double2 t = *(const double2*)p;
    a = (u64)__double_as_longlong(t.x);
    b = (u64)__double_as_longlong(t.y);
}

// ---------------- scratch (static device globals; no allocation) ----------------
__device__ float g_qkv   [BB*768*SL];
__device__ float g_qkvt  [BB*768*SL];
__device__ float g_attn  [BB*CC*SL];
__device__ float g_concat[(long)BB*512*SL];
__device__ float g_h     [BB*CC*SL];
__device__ float g_xc    [BB*CC*SG];
__device__ float g_qkvg  [BB*768*SG];
__device__ float g_qkvtg [BB*768*SG];
__device__ float g_attng [BB*CC*SG];
__device__ float g_g     [BB*CC*SG];

// ---------------- conv1x1 GEMM: Y[b,o,s] = sum_c W[o,c]*X[b,c,s] (+bias)(+gelu) ----
// Tile: 128(o) x 64(s) x 16(c). 256 threads (16x16), 8x4 microtile via f32x2.
__global__ void gemm_kernel(const float* __restrict__ X, const float* __restrict__ Wm,
                            const float* __restrict__ bias, float* __restrict__ Y,
                            int Cin, int Ssz, long xBS, long yBS, int doGelu)
{
    __shared__ __align__(16) float Ws[16][128];
    __shared__ __align__(16) float Xs[16][64];
    const int tx = threadIdx.x, ty = threadIdx.y;   // 16x16
    const int tid = ty * 16 + tx;
    const int s0 = blockIdx.x * 64;
    const int o0 = blockIdx.y * 128;
    const int b  = blockIdx.z;
    const float* Xb = X + (long)b * xBS;
    const bool full = (s0 + 64 <= Ssz);

    const int lw_o = tid >> 1;          // 0..127
    const int lw_c = (tid & 1) * 8;     // 0 or 8
    const int lx_c = tid >> 4;          // 0..15
    const int lx_s = (tid & 15) * 4;

    u64 acc[8][2];
    #pragma unroll
    for (int i = 0; i < 8; i++) { acc[i][0] = 0ULL; acc[i][1] = 0ULL; }

    for (int c0 = 0; c0 < Cin; c0 += 16) {
        {
            const float* wrow = Wm + (long)(o0 + lw_o) * Cin + c0 + lw_c;
            float4 w0 = *(const float4*)wrow;
            float4 w1 = *(const float4*)(wrow + 4);
            Ws[lw_c + 0][lw_o] = w0.x; Ws[lw_c + 1][lw_o] = w0.y;
            Ws[lw_c + 2][lw_o] = w0.z; Ws[lw_c + 3][lw_o] = w0.w;
            Ws[lw_c + 4][lw_o] = w1.x; Ws[lw_c + 5][lw_o] = w1.y;
            Ws[lw_c + 6][lw_o] = w1.z; Ws[lw_c + 7][lw_o] = w1.w;
        }
        {
            const float* xrow = Xb + (long)(c0 + lx_c) * Ssz + s0 + lx_s;
            if (full) {
                float4 xv = *(const float4*)xrow;
                Xs[lx_c][lx_s + 0] = xv.x; Xs[lx_c][lx_s + 1] = xv.y;
                Xs[lx_c][lx_s + 2] = xv.z; Xs[lx_c][lx_s + 3] = xv.w;
            } else {
                #pragma unroll
                for (int i = 0; i < 4; i++)
                    Xs[lx_c][lx_s + i] = (s0 + lx_s + i < Ssz) ? xrow[i] : 0.f;
            }
        }
        __syncthreads();

        #pragma unroll
        for (int c = 0; c < 16; c++) {
            u64 x01, x23;
            lds2(&Xs[c][tx * 4], x01, x23);
            float4 a0 = *(const float4*)&Ws[c][ty * 8];
            float4 a1 = *(const float4*)&Ws[c][ty * 8 + 4];
            u64 p;
            p = pack2(a0.x, a0.x); acc[0][0] = ffma2(p, x01, acc[0][0]); acc[0][1] = ffma2(p, x23, acc[0][1]);
            p = pack2(a0.y, a0.y); acc[1][0] = ffma2(p, x01, acc[1][0]); acc[1][1] = ffma2(p, x23, acc[1][1]);
            p = pack2(a0.z, a0.z); acc[2][0] = ffma2(p, x01, acc[2][0]); acc[2][1] = ffma2(p, x23, acc[2][1]);
            p = pack2(a0.w, a0.w); acc[3][0] = ffma2(p, x01, acc[3][0]); acc[3][1] = ffma2(p, x23, acc[3][1]);
            p = pack2(a1.x, a1.x); acc[4][0] = ffma2(p, x01, acc[4][0]); acc[4][1] = ffma2(p, x23, acc[4][1]);
            p = pack2(a1.y, a1.y); acc[5][0] = ffma2(p, x01, acc[5][0]); acc[5][1] = ffma2(p, x23, acc[5][1]);
            p = pack2(a1.z, a1.z); acc[6][0] = ffma2(p, x01, acc[6][0]); acc[6][1] = ffma2(p, x23, acc[6][1]);
            p = pack2(a1.w, a1.w); acc[7][0] = ffma2(p, x01, acc[7][0]); acc[7][1] = ffma2(p, x23, acc[7][1]);
        }
        __syncthreads();
    }

    #pragma unroll
    for (int i = 0; i < 8; i++) {
        int o = o0 + ty * 8 + i;
        float bv = bias ? bias[o] : 0.f;
        float2 p0 = unpack2(acc[i][0]);
        float2 p1 = unpack2(acc[i][1]);
        float vals[4] = {p0.x, p0.y, p1.x, p1.y};
        #pragma unroll
        for (int j = 0; j < 4; j++) {
            int s = s0 + tx * 4 + j;
            if (s < Ssz) {
                float v = vals[j] + bv;
                if (doGelu) v = 0.5f * v * (1.f + erff(v * 0.70710678118654752f));
                Y[(long)b * yBS + (long)o * Ssz + s] = v;
            }
        }
    }
}

// ---------- transpose [B,768,S] -> [B,3,8,S,32] with L2-norm on q/k ----------
__global__ void tnorm_kernel(const float* __restrict__ qkv, float* __restrict__ qkvt, int Ssz)
{
    __shared__ float sm[32][33];
    const int bp = blockIdx.y;
    const int b = bp / 24;
    const int rem = bp % 24;
    const int part = rem / 8;
    const int h = rem % 8;
    const int s0 = blockIdx.x * 32;
    const int tx = threadIdx.x, ty = threadIdx.y;

    {
        int s = s0 + tx;
        float v = 0.f;
        if (s < Ssz) v = qkv[((long)b * 768 + part * 256 + h * 32 + ty) * Ssz + s];
        sm[ty][tx] = v;
    }
    __syncthreads();

    float v = sm[tx][ty];
    if (part < 2) {
        float sq = v * v;
        #pragma unroll
        for (int off = 16; off; off >>= 1) sq += __shfl_xor_sync(0xffffffffu, sq, off);
        float n = sqrtf(sq);
        v = v / fmaxf(n, 1e-12f);
    }
    int s = s0 + ty;
    if (s < Ssz)
        qkvt[(((long)(b * 3 + part) * 8 + h) * Ssz + s) * 32 + tx] = v;
}

// ---------------- flash attention, 2 q-rows per thread, f32x2 packed math ----------------
// |logit| <= 0.177 (unit q,k): no running max. grid (B*H, ceil(S/256)), block 128.
// Rows: row_a = blk*256 + tid, row_b = row_a + 128. K/V smem loads + exp overhead
// amortized over 2 rows; fma pipe is the sole bottleneck.
__global__ void __launch_bounds__(128, 2)
attn_kernel(const float* __restrict__ qkvt, float* __restrict__ out, int Ssz)
{
    __shared__ __align__(16) float ks[64][32];
    __shared__ __align__(16) float vs[64][32];
    const int bh = blockIdx.x;
    const int b = bh >> 3, h = bh & 7;
    const long base = ((long)(b * 3) * HEADS + h) * Ssz * HD;
    const float* Q = qkvt + base;
    const float* K = Q + (long)HEADS * Ssz * HD;
    const float* V = Q + 2L * HEADS * Ssz * HD;
    const int tid = threadIdx.x;
    const int rowa = blockIdx.y * 256 + tid;
    const int rowb = rowa + 128;
    const bool va = rowa < Ssz;
    const bool vb = rowb < Ssz;

    const u64 sc2 = pack2(0.17677669529663687f, 0.17677669529663687f);

    u64 qa[16], qb[16];
    #pragma unroll
    for (int i = 0; i < 16; i++) { qa[i] = 0ULL; qb[i] = 0ULL; }
    if (va) {
        #pragma unroll
        for (int i = 0; i < 8; i++) {
            u64 t0, t1;
            lds2(Q + (long)rowa * 32 + i * 4, t0, t1);
            // pre-scale q by softmax scale (folds the per-j multiply)
            qa[2 * i]     = ffma2(t0, sc2, 0ULL);
            qa[2 * i + 1] = ffma2(t1, sc2, 0ULL);
        }
    }
    if (vb) {
        #pragma unroll
        for (int i = 0; i < 8; i++) {
            u64 t0, t1;
            lds2(Q + (long)rowb * 32 + i * 4, t0, t1);
            qb[2 * i]     = ffma2(t0, sc2, 0ULL);
            qb[2 * i + 1] = ffma2(t1, sc2, 0ULL);
        }
    }

    u64 aa[16], ab[16];
    #pragma unroll
    for (int i = 0; i < 16; i++) { aa[i] = 0ULL; ab[i] = 0ULL; }
    float la = 0.f, lb = 0.f;

    for (int j0 = 0; j0 < Ssz; j0 += 64) {
        int cnt = min(64, Ssz - j0);
        int nf4 = cnt * 8;
        const float4* kp = (const float4*)(K + (long)j0 * 32);
        const float4* vp = (const float4*)(V + (long)j0 * 32);
        #pragma unroll
        for (int t = 0; t < 4; t++) {
            int i = tid + t * 128;
            if (i < nf4) { ((float4*)ks)[i] = kp[i]; ((float4*)vs)[i] = vp[i]; }
        }
        __syncthreads();

        for (int j = 0; j < cnt; j++) {
            // load K row once, dot for both q rows
            u64 kt[16];
            #pragma unroll
            for (int i = 0; i < 8; i++) lds2(&ks[j][i * 4], kt[2 * i], kt[2 * i + 1]);

            u64 da0 = 0ULL, da1 = 0ULL, db0 = 0ULL, db1 = 0ULL;
            #pragma unroll
            for (int i = 0; i < 16; i += 2) {
                da0 = ffma2(qa[i], kt[i], da0);
                da1 = ffma2(qa[i + 1], kt[i + 1], da1);
                db0 = ffma2(qb[i], kt[i], db0);
                db1 = ffma2(qb[i + 1], kt[i + 1], db1);
            }
            float2 ea0 = unpack2(da0), ea1 = unpack2(da1);
            float2 eb0 = unpack2(db0), eb1 = unpack2(db1);
            float pa = __expf((ea0.x + ea0.y) + (ea1.x + ea1.y));
            float pb = __expf((eb0.x + eb0.y) + (eb1.x + eb1.y));
            la += pa; lb += pb;
            u64 pa2 = pack2(pa, pa);
            u64 pb2 = pack2(pb, pb);

            // load V row once, accumulate both rows
            u64 vt[16];
            #pragma unroll
            for (int i = 0; i < 8; i++) lds2(&vs[j][i * 4], vt[2 * i], vt[2 * i + 1]);
            #pragma unroll
            for (int i = 0; i < 16; i++) {
                aa[i] = ffma2(pa2, vt[i], aa[i]);
                ab[i] = ffma2(pb2, vt[i], ab[i]);
            }
        }
        __syncthreads();
    }

    long ob = (long)b * CC + h * HD;
    if (va) {
        float inv = 1.f / la;
        #pragma unroll
        for (int i = 0; i < 16; i++) {
            float2 t = unpack2(aa[i]);
            out[(ob + 2 * i)     * (long)Ssz + rowa] = t.x * inv;
            out[(ob + 2 * i + 1) * (long)Ssz + rowa] = t.y * inv;
        }
    }
    if (vb) {
        float inv = 1.f / lb;
        #pragma unroll
        for (int i = 0; i < 16; i++) {
            float2 t = unpack2(ab[i]);
            out[(ob + 2 * i)     * (long)Ssz + rowb] = t.x * inv;
            out[(ob + 2 * i + 1) * (long)Ssz + rowb] = t.y * inv;
        }
    }
}

// ---------------- 4x4 average pool ----------------
__global__ void avgpool_kernel(const float* __restrict__ x, float* __restrict__ xc)
{
    int idx = blockIdx.x * blockDim.x + threadIdx.x;
    if (idx >= BB * CC * SG) return;
    int p = idx % SG;
    int c = (idx / SG) % CC;
    int b = idx / (SG * CC);
    int i = p / 12, j = p % 12;
    const float* xp = x + ((long)b * CC + c) * SL;
    float s = 0.f;
    #pragma unroll
    for (int dy = 0; dy < 4; dy++)
        #pragma unroll
        for (int dx = 0; dx < 4; dx++)
            s += xp[(i * 4 + dy) * 48 + j * 4 + dx];
    xc[idx] = s * (1.f / 16.f);
}

// ---------------- bilinear 12x12 -> 48x48 into concat ch 256..511 ----------------
__global__ void upsample_kernel(const float* __restrict__ g, float* __restrict__ concat)
{
    int idx = blockIdx.x * blockDim.x + threadIdx.x;
    if (idx >= BB * CC * SL) return;
    int p = idx % SL;
    int c = (idx / SL) % CC;
    int b = idx / (SL * CC);
    int y = p / 48, x = p % 48;
    float fy = (y + 0.5f) * 0.25f - 0.5f;
    float fx = (x + 0.5f) * 0.25f - 0.5f;
    int y0 = (int)floorf(fy), x0 = (int)floorf(fx);
    float wy = fy - y0, wx = fx - x0;
    int ya = min(11, max(0, y0)), yb = min(11, max(0, y0 + 1));
    int xa = min(11, max(0, x0)), xb = min(11, max(0, x0 + 1));
    const float* gp = g + ((long)b * CC + c) * SG;
    float v00 = gp[ya * 12 + xa], v01 = gp[ya * 12 + xb];
    float v10 = gp[yb * 12 + xa], v11 = gp[yb * 12 + xb];
    float v = (1.f - wy) * ((1.f - wx) * v00 + wx * v01)
            +        wy  * ((1.f - wx) * v10 + wx * v11);
    concat[((long)b * 512 + 256 + c) * SL + p] = v;
}

// ---------------- launch ----------------
extern "C" void kernel_launch(void* const* d_in, const int* in_sizes, int n_in,
                              void* d_out, int out_size)
{
    const float* x        = (const float*)d_in[0];
    const float* w_qkv_l  = (const float*)d_in[1];
    const float* w_proj_l = (const float*)d_in[2];
    const float* b_proj_l = (const float*)d_in[3];
    const float* w_qkv_g  = (const float*)d_in[4];
    const float* w_proj_g = (const float*)d_in[5];
    const float* b_proj_g = (const float*)d_in[6];
    const float* w_f1     = (const float*)d_in[7];
    const float* b_f1     = (const float*)d_in[8];
    const float* w_f2     = (const float*)d_in[9];
    const float* b_f2     = (const float*)d_in[10];
    float* out = (float*)d_out;

    float *qkv, *qkvt, *attn, *concat, *hbuf, *xc, *qkvg, *qkvtg, *attng, *gg;
    cudaGetSymbolAddress((void**)&qkv,    g_qkv);
    cudaGetSymbolAddress((void**)&qkvt,   g_qkvt);
    cudaGetSymbolAddress((void**)&attn,   g_attn);
    cudaGetSymbolAddress((void**)&concat, g_concat);
    cudaGetSymbolAddress((void**)&hbuf,   g_h);
    cudaGetSymbolAddress((void**)&xc,     g_xc);
    cudaGetSymbolAddress((void**)&qkvg,   g_qkvg);
    cudaGetSymbolAddress((void**)&qkvtg,  g_qkvtg);
    cudaGetSymbolAddress((void**)&attng,  g_attng);
    cudaGetSymbolAddress((void**)&gg,     g_g);

    dim3 blk(16, 16);

    // local branch
    gemm_kernel<<<dim3(SL / 64, 768 / 128, BB), blk>>>(x, w_qkv_l, nullptr, qkv,
                                                       256, SL, 256L * SL, 768L * SL, 0);
    tnorm_kernel<<<dim3(SL / 32, BB * 24), dim3(32, 32)>>>(qkv, qkvt, SL);
    attn_kernel<<<dim3(BB * HEADS, (SL + 255) / 256), 128>>>(qkvt, attn, SL);
    gemm_kernel<<<dim3(SL / 64, 256 / 128, BB), blk>>>(attn, w_proj_l, b_proj_l, concat,
                                                       256, SL, 256L * SL, 512L * SL, 0);

    // global branch
    avgpool_kernel<<<(BB * CC * SG + 255) / 256, 256>>>(x, xc);
    gemm_kernel<<<dim3((SG + 63) / 64, 768 / 128, BB), blk>>>(xc, w_qkv_g, nullptr, qkvg,
                                                              256, SG, 256L * SG, 768L * SG, 0);
    tnorm_kernel<<<dim3((SG + 31) / 32, BB * 24), dim3(32, 32)>>>(qkvg, qkvtg, SG);
    attn_kernel<<<dim3(BB * HEADS, (SG + 255) / 256), 128>>>(qkvtg, attng, SG);
    gemm_kernel<<<dim3((SG + 63) / 64, 256 / 128, BB), blk>>>(attng, w_proj_g, b_proj_g, gg,
                                                              256, SG, 256L * SG, 256L * SG, 0);
    upsample_kernel<<<(BB * CC * SL + 255) / 256, 256>>>(gg, concat);

    // fusion head
    gemm_kernel<<<dim3(SL / 64, 256 / 128, BB), blk>>>(concat, w_f1, b_f1, hbuf,
                                                       512, SL, 512L * SL, 256L * SL, 1);
    gemm_kernel<<<dim3(SL / 64, 256 / 128, BB), blk>>>(hbuf, w_f2, b_f2, out,
                                                       256, SL, 256L * SL, 256L * SL, 0);
}